// round 1
// baseline (speedup 1.0000x reference)
#include <cuda_runtime.h>
#include <math.h>

// Problem constants
#define R_    2048
#define C_    1024
#define NCH   8
// 64 softmax columns per row (CH*BA)

// K2 tiling
#define K2_RPB    16          // rows per block in the D^T @ lq pass
#define K2_BLOCKS (R_ / K2_RPB)   // 128

// Scratch (no allocations allowed -> device globals)
__device__ float g_lq[R_ * NCH];                 // log prod_ba (1-P) per (row, ch)   64KB
__device__ float g_Lpart[K2_BLOCKS * NCH * C_];  // partial log-sums per row-block     4MB
__device__ float g_colch[NCH * C_];              // col_ch, channel-major              32KB
__device__ float g_pA[256 * 64];                 // per-block partial  sum_r P*s
__device__ float g_pB[256 * 64];                 // per-block partial  sum_r P
__device__ float g_pSel[256];                    // per-block partial  row-sel count

// ---------------------------------------------------------------------------
// K1: one warp per row. Softmax over 64 logits, write P, compute
//     lq[r][ch] = sum_ba log1p(-P), s[r] = row-sum of D, and per-block
//     partial reductions for nnz / psum / sel.
// ---------------------------------------------------------------------------
__global__ __launch_bounds__(256) void k1_row(const float* __restrict__ W,
                                              const float* __restrict__ D,
                                              const float* __restrict__ G,
                                              float* __restrict__ outP)
{
    const int warp = threadIdx.x >> 5;
    const int lane = threadIdx.x & 31;
    const int r    = blockIdx.x * 8 + warp;

    const float2* W2 = reinterpret_cast<const float2*>(W);
    const float2* G2 = reinterpret_cast<const float2*>(G);

    float2 w  = W2[r * 32 + lane];
    float2 gv = G2[r * 32 + lane];
    float e0 = w.x + gv.x;
    float e1 = w.y + gv.y;

    float m = fmaxf(e0, e1);
    #pragma unroll
    for (int o = 16; o > 0; o >>= 1)
        m = fmaxf(m, __shfl_xor_sync(0xFFFFFFFFu, m, o));

    float x0 = expf(e0 - m);
    float x1 = expf(e1 - m);
    float s  = x0 + x1;
    #pragma unroll
    for (int o = 16; o > 0; o >>= 1)
        s += __shfl_xor_sync(0xFFFFFFFFu, s, o);

    const float inv = 1.0f / s;          // == max(P) since exp(0)=1 at argmax
    const float p0  = x0 * inv;
    const float p1  = x1 * inv;

    reinterpret_cast<float2*>(outP)[r * 32 + lane] = make_float2(p0, p1);

    // log prod_ba (1-P): per-lane pair, then reduce over the 4-lane quad = one channel
    float lq = log1pf(-p0) + log1pf(-p1);
    lq += __shfl_xor_sync(0xFFFFFFFFu, lq, 1);
    lq += __shfl_xor_sync(0xFFFFFFFFu, lq, 2);
    if ((lane & 3) == 0)
        g_lq[r * NCH + (lane >> 2)] = lq;

    // s[r] = sum_c D[r, c]
    const float4* D4 = reinterpret_cast<const float4*>(D + (size_t)r * C_);
    float ds = 0.0f;
    #pragma unroll
    for (int k = 0; k < 8; k++) {
        float4 v = D4[lane + k * 32];
        ds += (v.x + v.y) + (v.z + v.w);
    }
    #pragma unroll
    for (int o = 16; o > 0; o >>= 1)
        ds += __shfl_xor_sync(0xFFFFFFFFu, ds, o);

    // block-level partial reductions
    __shared__ float sA[8][64];
    __shared__ float sB[8][64];
    __shared__ float sSel[8];
    sA[warp][2 * lane]     = p0 * ds;
    sA[warp][2 * lane + 1] = p1 * ds;
    sB[warp][2 * lane]     = p0;
    sB[warp][2 * lane + 1] = p1;
    if (lane == 0) sSel[warp] = (inv > 0.99f) ? 1.0f : 0.0f;
    __syncthreads();

    const int t = threadIdx.x;
    if (t < 64) {
        float a = 0.0f, b = 0.0f;
        #pragma unroll
        for (int w2 = 0; w2 < 8; w2++) { a += sA[w2][t]; b += sB[w2][t]; }
        g_pA[blockIdx.x * 64 + t] = a;
        g_pB[blockIdx.x * 64 + t] = b;
    }
    if (t == 0) {
        float ss = 0.0f;
        #pragma unroll
        for (int w2 = 0; w2 < 8; w2++) ss += sSel[w2];
        g_pSel[blockIdx.x] = ss;
    }
}

// ---------------------------------------------------------------------------
// K2: Lpart[blk][ch][c] = sum over 16 rows of D[r,c] * lq[r,ch].
// 256 threads x 4 cols (float4) = all 1024 columns; 128 row-blocks.
// D second read -> L2 resident after K1. FMA-issue bound otherwise.
// ---------------------------------------------------------------------------
__global__ __launch_bounds__(256) void k2_colprod(const float* __restrict__ D)
{
    __shared__ float slq[K2_RPB][NCH];
    const int t  = threadIdx.x;
    const int r0 = blockIdx.x * K2_RPB;

    if (t < K2_RPB * NCH)
        slq[t >> 3][t & 7] = g_lq[r0 * NCH + t];
    __syncthreads();

    float acc0[NCH], acc1[NCH], acc2[NCH], acc3[NCH];
    #pragma unroll
    for (int ch = 0; ch < NCH; ch++) { acc0[ch]=0.f; acc1[ch]=0.f; acc2[ch]=0.f; acc3[ch]=0.f; }

    const float4* D4 = reinterpret_cast<const float4*>(D);
    #pragma unroll 4
    for (int rl = 0; rl < K2_RPB; rl++) {
        float4 d = D4[(size_t)(r0 + rl) * 256 + t];
        #pragma unroll
        for (int ch = 0; ch < NCH; ch++) {
            float l = slq[rl][ch];
            acc0[ch] = fmaf(d.x, l, acc0[ch]);
            acc1[ch] = fmaf(d.y, l, acc1[ch]);
            acc2[ch] = fmaf(d.z, l, acc2[ch]);
            acc3[ch] = fmaf(d.w, l, acc3[ch]);
        }
    }

    const int c0 = t * 4;
    #pragma unroll
    for (int ch = 0; ch < NCH; ch++) {
        float4 v = make_float4(acc0[ch], acc1[ch], acc2[ch], acc3[ch]);
        *reinterpret_cast<float4*>(
            &g_Lpart[((size_t)blockIdx.x * NCH + ch) * C_ + c0]) = v;
    }
}

// ---------------------------------------------------------------------------
// K3: reduce the 128 row-block partials, col_ch = 1 - exp(L).
// 8192 outputs, fully coalesced across threads.
// ---------------------------------------------------------------------------
__global__ __launch_bounds__(256) void k3_reduce()
{
    const int o = blockIdx.x * 256 + threadIdx.x;   // 0..8191  (ch*1024 + c)
    float s = 0.0f;
    #pragma unroll 8
    for (int k = 0; k < K2_BLOCKS; k++)
        s += g_Lpart[k * (NCH * C_) + o];
    g_colch[o] = 1.0f - expf(s);
}

// ---------------------------------------------------------------------------
// K4: final scalars. Output layout (float32, concatenated tuple):
//   P[131072] | tot[8] | max_nnz[8] | num_col[8] | num_row[8] |
//   nnz_ch_ba[64] | col_density[8] | num_row_sel[1]
// ---------------------------------------------------------------------------
__global__ __launch_bounds__(256) void k4_final(float* __restrict__ out)
{
    const int t = threadIdx.x;
    __shared__ float nnz[64], psum[64];
    __shared__ float ncol[NCH], nrow[NCH], mx[NCH], nsum[NCH];

    if (t < 64) {
        float a = 0.0f, b = 0.0f;
        for (int k = 0; k < 256; k++) {
            a += g_pA[k * 64 + t];
            b += g_pB[k * 64 + t];
        }
        nnz[t] = a; psum[t] = b;
        out[131104 + t] = a;                 // nnz_ch_ba
    }
    __syncthreads();

    // one warp per channel sums col_ch over 1024 columns
    const int ch = t >> 5, lane = t & 31;
    float nc = 0.0f;
    for (int c = lane; c < C_; c += 32) nc += g_colch[ch * C_ + c];
    #pragma unroll
    for (int o = 16; o > 0; o >>= 1) nc += __shfl_xor_sync(0xFFFFFFFFu, nc, o);
    if (lane == 0) ncol[ch] = nc;

    if (t < NCH) {
        float m = -1e30f, rs = 0.0f, ns = 0.0f;
        #pragma unroll
        for (int ba = 0; ba < 8; ba++) {
            float v = nnz[t * 8 + ba];
            m = fmaxf(m, v);
            ns += v;
            rs += psum[t * 8 + ba];
        }
        mx[t] = m; nrow[t] = rs; nsum[t] = ns;
    }
    __syncthreads();

    if (t < NCH) {
        float ncl = ncol[t];
        out[131072 + t] = mx[t] + ncl + nrow[t];       // tot_ch
        out[131080 + t] = mx[t];                       // max_nnz_ch
        out[131088 + t] = ncl;                         // num_col_ch
        out[131096 + t] = nrow[t];                     // num_row_ch
        out[131168 + t] = nsum[t] / nrow[t] / ncl;     // col_density_ch
    }
    if (t == 0) {
        float ss = 0.0f;
        for (int k = 0; k < 256; k++) ss += g_pSel[k];
        out[131176] = ss;                              // num_row_sel
    }
}

// ---------------------------------------------------------------------------
extern "C" void kernel_launch(void* const* d_in, const int* in_sizes, int n_in,
                              void* d_out, int out_size)
{
    const float* W = (const float*)d_in[0];   // [2048, 64]
    const float* D = (const float*)d_in[1];   // [2048, 1024]
    const float* G = (const float*)d_in[2];   // [2048, 64]
    // d_in[3] = i, unused by the math
    float* out = (float*)d_out;

    k1_row<<<R_ / 8, 256>>>(W, D, G, out);
    k2_colprod<<<K2_BLOCKS, 256>>>(D);
    k3_reduce<<<(NCH * C_) / 256, 256>>>();
    k4_final<<<1, 256>>>(out);
}

// round 2
// speedup vs baseline: 1.9522x; 1.9522x over previous
#include <cuda_runtime.h>
#include <math.h>

// Problem constants
#define R_    2048
#define C_    1024
#define NCH   8
// 64 softmax columns per row (CH*BA)

// K2 tiling
#define K2_RPB    16               // rows per block in the D^T @ lq pass
#define K2_BLOCKS (R_ / K2_RPB)    // 128
#define K3_BLOCKS 32

// Scratch (no allocations allowed -> device globals)
__device__ float g_lq[R_ * NCH];                 // log prod_ba (1-P) per (row, ch)
__device__ float g_Lpart[K2_BLOCKS * NCH * C_];  // partial log-sums per row-block (4MB)
__device__ float g_pA[64 * 256];                 // TRANSPOSED: [col64][block256] sum_r P*s
__device__ float g_pB[64 * 256];                 // TRANSPOSED: [col64][block256] sum_r P
__device__ float g_pSel[256];                    // per-block partial row-sel count
__device__ float g_nnz[64];                      // reduced nnz_ch_ba
__device__ float g_psum[64];                     // reduced sum_r P per (ch,ba)
__device__ float g_ncolPart[K3_BLOCKS];          // per-K3-block colch sums
__device__ float g_selv;                         // reduced row-sel count
__device__ unsigned int g_count = 0;             // K3 completion ticket (self-resetting)

// ---------------------------------------------------------------------------
// K1: one warp per row. Softmax over 64 logits, write P, compute
//     lq[r][ch] = sum_ba log1p(-P), s[r] = row-sum of D, and per-block
//     partial reductions for nnz / psum / sel.
// ---------------------------------------------------------------------------
__global__ __launch_bounds__(256) void k1_row(const float* __restrict__ W,
                                              const float* __restrict__ D,
                                              const float* __restrict__ G,
                                              float* __restrict__ outP)
{
    const int warp = threadIdx.x >> 5;
    const int lane = threadIdx.x & 31;
    const int r    = blockIdx.x * 8 + warp;

    const float2* W2 = reinterpret_cast<const float2*>(W);
    const float2* G2 = reinterpret_cast<const float2*>(G);

    float2 w  = W2[r * 32 + lane];
    float2 gv = G2[r * 32 + lane];
    float e0 = w.x + gv.x;
    float e1 = w.y + gv.y;

    float m = fmaxf(e0, e1);
    #pragma unroll
    for (int o = 16; o > 0; o >>= 1)
        m = fmaxf(m, __shfl_xor_sync(0xFFFFFFFFu, m, o));

    float x0 = expf(e0 - m);
    float x1 = expf(e1 - m);
    float s  = x0 + x1;
    #pragma unroll
    for (int o = 16; o > 0; o >>= 1)
        s += __shfl_xor_sync(0xFFFFFFFFu, s, o);

    const float inv = 1.0f / s;          // == max(P) since exp(0)=1 at argmax
    const float p0  = x0 * inv;
    const float p1  = x1 * inv;

    reinterpret_cast<float2*>(outP)[r * 32 + lane] = make_float2(p0, p1);

    // log prod_ba (1-P): per-lane pair, then reduce the 4-lane quad = one channel
    float lq = log1pf(-p0) + log1pf(-p1);
    lq += __shfl_xor_sync(0xFFFFFFFFu, lq, 1);
    lq += __shfl_xor_sync(0xFFFFFFFFu, lq, 2);
    if ((lane & 3) == 0)
        g_lq[r * NCH + (lane >> 2)] = lq;

    // s[r] = sum_c D[r, c]
    const float4* D4 = reinterpret_cast<const float4*>(D + (size_t)r * C_);
    float ds = 0.0f;
    #pragma unroll
    for (int k = 0; k < 8; k++) {
        float4 v = D4[lane + k * 32];
        ds += (v.x + v.y) + (v.z + v.w);
    }
    #pragma unroll
    for (int o = 16; o > 0; o >>= 1)
        ds += __shfl_xor_sync(0xFFFFFFFFu, ds, o);

    // block-level partial reductions
    __shared__ float sA[8][64];
    __shared__ float sB[8][64];
    __shared__ float sSel[8];
    sA[warp][2 * lane]     = p0 * ds;
    sA[warp][2 * lane + 1] = p1 * ds;
    sB[warp][2 * lane]     = p0;
    sB[warp][2 * lane + 1] = p1;
    if (lane == 0) sSel[warp] = (inv > 0.99f) ? 1.0f : 0.0f;
    __syncthreads();

    const int t = threadIdx.x;
    if (t < 64) {
        float a = 0.0f, b = 0.0f;
        #pragma unroll
        for (int w2 = 0; w2 < 8; w2++) { a += sA[w2][t]; b += sB[w2][t]; }
        g_pA[t * 256 + blockIdx.x] = a;      // transposed for coalesced K3 reads
        g_pB[t * 256 + blockIdx.x] = b;
    }
    if (t == 0) {
        float ss = 0.0f;
        #pragma unroll
        for (int w2 = 0; w2 < 8; w2++) ss += sSel[w2];
        g_pSel[blockIdx.x] = ss;
    }
}

// ---------------------------------------------------------------------------
// K2: Lpart[blk][ch][c] = sum over 16 rows of D[r,c] * lq[r,ch].
// 256 threads x 4 cols (float4) = all 1024 columns; 128 row-blocks.
// ---------------------------------------------------------------------------
__global__ __launch_bounds__(256) void k2_colprod(const float* __restrict__ D)
{
    __shared__ float slq[K2_RPB][NCH];
    const int t  = threadIdx.x;
    const int r0 = blockIdx.x * K2_RPB;

    if (t < K2_RPB * NCH)
        slq[t >> 3][t & 7] = g_lq[r0 * NCH + t];
    __syncthreads();

    float acc0[NCH], acc1[NCH], acc2[NCH], acc3[NCH];
    #pragma unroll
    for (int ch = 0; ch < NCH; ch++) { acc0[ch]=0.f; acc1[ch]=0.f; acc2[ch]=0.f; acc3[ch]=0.f; }

    const float4* D4 = reinterpret_cast<const float4*>(D);
    #pragma unroll 4
    for (int rl = 0; rl < K2_RPB; rl++) {
        float4 d = D4[(size_t)(r0 + rl) * 256 + t];
        #pragma unroll
        for (int ch = 0; ch < NCH; ch++) {
            float l = slq[rl][ch];
            acc0[ch] = fmaf(d.x, l, acc0[ch]);
            acc1[ch] = fmaf(d.y, l, acc1[ch]);
            acc2[ch] = fmaf(d.z, l, acc2[ch]);
            acc3[ch] = fmaf(d.w, l, acc3[ch]);
        }
    }

    const int c0 = t * 4;
    #pragma unroll
    for (int ch = 0; ch < NCH; ch++) {
        float4 v = make_float4(acc0[ch], acc1[ch], acc2[ch], acc3[ch]);
        *reinterpret_cast<float4*>(
            &g_Lpart[((size_t)blockIdx.x * NCH + ch) * C_ + c0]) = v;
    }
}

// ---------------------------------------------------------------------------
// K3: reduce the 128 row-block partials -> col_ch = 1 - exp(L); per-block
// colch sums; warp-parallel reductions of pA/pB/sel; last block finalizes.
// Output layout (float32, concatenated tuple):
//   P[131072] | tot[8] | max_nnz[8] | num_col[8] | num_row[8] |
//   nnz_ch_ba[64] | col_density[8] | num_row_sel[1]
// ---------------------------------------------------------------------------
__global__ __launch_bounds__(256) void k3_reduce_final(float* __restrict__ out)
{
    const int t    = threadIdx.x;
    const int lane = t & 31;
    const int wid  = t >> 5;
    const int o    = blockIdx.x * 256 + t;   // (ch*1024 + c); block covers one ch

    // ---- sum 128 Lpart partials with 4-way MLP ----
    float s0 = 0.f, s1 = 0.f, s2 = 0.f, s3 = 0.f;
    #pragma unroll
    for (int k = 0; k < K2_BLOCKS; k += 4) {
        s0 += g_Lpart[(k + 0) * (NCH * C_) + o];
        s1 += g_Lpart[(k + 1) * (NCH * C_) + o];
        s2 += g_Lpart[(k + 2) * (NCH * C_) + o];
        s3 += g_Lpart[(k + 3) * (NCH * C_) + o];
    }
    float colch = 1.0f - expf((s0 + s1) + (s2 + s3));

    // ---- block-sum of colch (all 256 lanes belong to the same channel) ----
    float v = colch;
    #pragma unroll
    for (int off = 16; off > 0; off >>= 1)
        v += __shfl_xor_sync(0xFFFFFFFFu, v, off);
    __shared__ float wsum[8];
    if (lane == 0) wsum[wid] = v;

    // ---- warp-parallel reductions of K1 partials (coalesced, transposed) ----
    const int gw = blockIdx.x * 8 + wid;     // global warp id 0..255
    if (gw < 64) {
        float a = 0.f;
        #pragma unroll
        for (int k = 0; k < 8; k++) a += g_pA[gw * 256 + lane + k * 32];
        #pragma unroll
        for (int off = 16; off > 0; off >>= 1)
            a += __shfl_xor_sync(0xFFFFFFFFu, a, off);
        if (lane == 0) g_nnz[gw] = a;
    } else if (gw < 128) {
        float a = 0.f;
        #pragma unroll
        for (int k = 0; k < 8; k++) a += g_pB[(gw - 64) * 256 + lane + k * 32];
        #pragma unroll
        for (int off = 16; off > 0; off >>= 1)
            a += __shfl_xor_sync(0xFFFFFFFFu, a, off);
        if (lane == 0) g_psum[gw - 64] = a;
    } else if (gw == 128) {
        float a = 0.f;
        #pragma unroll
        for (int k = 0; k < 8; k++) a += g_pSel[lane + k * 32];
        #pragma unroll
        for (int off = 16; off > 0; off >>= 1)
            a += __shfl_xor_sync(0xFFFFFFFFu, a, off);
        if (lane == 0) g_selv = a;
    }

    __syncthreads();
    if (t == 0) {
        float bs = 0.f;
        #pragma unroll
        for (int w2 = 0; w2 < 8; w2++) bs += wsum[w2];
        g_ncolPart[blockIdx.x] = bs;
    }

    // ---- completion ticket: last block finalizes ----
    __shared__ int isLast;
    __threadfence();
    if (t == 0) {
        unsigned int old = atomicAdd(&g_count, 1u);
        isLast = (old == K3_BLOCKS - 1) ? 1 : 0;
        if (isLast) g_count = 0;             // reset for next graph replay
    }
    __syncthreads();
    if (!isLast) return;
    __threadfence();                          // acquire other blocks' writes

    if (t < 64) out[131104 + t] = g_nnz[t];   // nnz_ch_ba

    if (t < NCH) {
        float m = -1e30f, ns = 0.f, rs = 0.f;
        #pragma unroll
        for (int ba = 0; ba < 8; ba++) {
            float nv = g_nnz[t * 8 + ba];
            m  = fmaxf(m, nv);
            ns += nv;
            rs += g_psum[t * 8 + ba];
        }
        float ncl = g_ncolPart[t * 4] + g_ncolPart[t * 4 + 1]
                  + g_ncolPart[t * 4 + 2] + g_ncolPart[t * 4 + 3];
        out[131072 + t] = m + ncl + rs;       // tot_ch
        out[131080 + t] = m;                  // max_nnz_ch
        out[131088 + t] = ncl;                // num_col_ch
        out[131096 + t] = rs;                 // num_row_ch
        out[131168 + t] = ns / rs / ncl;      // col_density_ch
    }
    if (t == 0) out[131176] = g_selv;         // num_row_sel
}

// ---------------------------------------------------------------------------
extern "C" void kernel_launch(void* const* d_in, const int* in_sizes, int n_in,
                              void* d_out, int out_size)
{
    const float* W = (const float*)d_in[0];   // [2048, 64]
    const float* D = (const float*)d_in[1];   // [2048, 1024]
    const float* G = (const float*)d_in[2];   // [2048, 64]
    // d_in[3] = i, unused by the math
    float* out = (float*)d_out;

    k1_row<<<R_ / 8, 256>>>(W, D, G, out);
    k2_colprod<<<K2_BLOCKS, 256>>>(D);
    k3_reduce_final<<<K3_BLOCKS, 256>>>(out);
}

// round 3
// speedup vs baseline: 2.0733x; 1.0620x over previous
#include <cuda_runtime.h>
#include <math.h>

// Problem constants
#define R_    2048
#define C_    1024
#define NCH   8

#define RPB      16               // rows per fused block
#define NBLK     (R_ / RPB)       // 128
#define K3_BLOCKS 32

// Scratch (no allocations allowed -> device globals)
__device__ float g_Lpart[NBLK * NCH * C_];   // partial log-sums per row-block (4MB)
__device__ float g_pA[64 * NBLK];            // TRANSPOSED: [col64][block128] sum_r P*s
__device__ float g_pB[64 * NBLK];            // TRANSPOSED: [col64][block128] sum_r P
__device__ float g_pSel[NBLK];               // per-block partial row-sel count
__device__ float g_nnz[64];                  // reduced nnz_ch_ba
__device__ float g_psum[64];                 // reduced sum_r P per (ch,ba)
__device__ float g_ncolPart[K3_BLOCKS];      // per-K3-block colch sums
__device__ float g_selv;                     // reduced row-sel count
__device__ unsigned int g_count = 0;         // K3 completion ticket (self-resetting)

// ---------------------------------------------------------------------------
// KF (fused K1+K2): each block owns 16 rows.
//  Stage A: 8 warps x 2 rows -> softmax over 64, write P, stage P/lq/sel in smem.
//  Stage B: stream the 16x1024 D tile ONCE; per-thread 4 cols: 8-ch log-product
//           FMAs + per-row sums from the same loads.
//  Stage C: write Lpart + per-block pA/pB/sel partials.
// ---------------------------------------------------------------------------
__global__ __launch_bounds__(256) void kf_fused(const float* __restrict__ W,
                                                const float* __restrict__ D,
                                                const float* __restrict__ G,
                                                float* __restrict__ outP)
{
    __shared__ float sP[RPB][64];
    __shared__ float slq[RPB][NCH];
    __shared__ float sds[RPB][8];
    __shared__ float sSel[RPB];
    __shared__ float sS[RPB];

    const int t    = threadIdx.x;
    const int wid  = t >> 5;
    const int lane = t & 31;
    const int r0   = blockIdx.x * RPB;

    const float2* W2 = reinterpret_cast<const float2*>(W);
    const float2* G2 = reinterpret_cast<const float2*>(G);

    // ---- Stage A: softmax, 2 rows per warp ----
    #pragma unroll
    for (int rr = 0; rr < 2; rr++) {
        const int rl = wid * 2 + rr;
        const int r  = r0 + rl;

        float2 w  = W2[r * 32 + lane];
        float2 gv = G2[r * 32 + lane];
        float e0 = w.x + gv.x;
        float e1 = w.y + gv.y;

        float m = fmaxf(e0, e1);
        #pragma unroll
        for (int o = 16; o > 0; o >>= 1)
            m = fmaxf(m, __shfl_xor_sync(0xFFFFFFFFu, m, o));

        float x0 = expf(e0 - m);
        float x1 = expf(e1 - m);
        float s  = x0 + x1;
        #pragma unroll
        for (int o = 16; o > 0; o >>= 1)
            s += __shfl_xor_sync(0xFFFFFFFFu, s, o);

        const float inv = 1.0f / s;      // == max(P): exp(0)=1 at the argmax
        const float p0  = x0 * inv;
        const float p1  = x1 * inv;

        reinterpret_cast<float2*>(outP)[r * 32 + lane] = make_float2(p0, p1);
        sP[rl][2 * lane]     = p0;
        sP[rl][2 * lane + 1] = p1;

        float lq = log1pf(-p0) + log1pf(-p1);
        lq += __shfl_xor_sync(0xFFFFFFFFu, lq, 1);
        lq += __shfl_xor_sync(0xFFFFFFFFu, lq, 2);
        if ((lane & 3) == 0) slq[rl][lane >> 2] = lq;
        if (lane == 0) sSel[rl] = (inv > 0.99f) ? 1.0f : 0.0f;
    }
    __syncthreads();

    // ---- Stage B: single pass over the D tile ----
    float acc0[NCH], acc1[NCH], acc2[NCH], acc3[NCH];
    #pragma unroll
    for (int ch = 0; ch < NCH; ch++) { acc0[ch]=0.f; acc1[ch]=0.f; acc2[ch]=0.f; acc3[ch]=0.f; }

    const float4* D4 = reinterpret_cast<const float4*>(D);
    #pragma unroll 4
    for (int rl = 0; rl < RPB; rl++) {
        float4 d = D4[(size_t)(r0 + rl) * 256 + t];
        float ds = (d.x + d.y) + (d.z + d.w);
        #pragma unroll
        for (int ch = 0; ch < NCH; ch++) {
            float l = slq[rl][ch];
            acc0[ch] = fmaf(d.x, l, acc0[ch]);
            acc1[ch] = fmaf(d.y, l, acc1[ch]);
            acc2[ch] = fmaf(d.z, l, acc2[ch]);
            acc3[ch] = fmaf(d.w, l, acc3[ch]);
        }
        #pragma unroll
        for (int o = 16; o > 0; o >>= 1)
            ds += __shfl_xor_sync(0xFFFFFFFFu, ds, o);
        if (lane == 0) sds[rl][wid] = ds;
    }

    // ---- Stage C: write partials ----
    const int c0 = t * 4;
    #pragma unroll
    for (int ch = 0; ch < NCH; ch++) {
        float4 v = make_float4(acc0[ch], acc1[ch], acc2[ch], acc3[ch]);
        *reinterpret_cast<float4*>(
            &g_Lpart[((size_t)blockIdx.x * NCH + ch) * C_ + c0]) = v;
    }
    __syncthreads();

    if (t < RPB) {
        float v = 0.f;
        #pragma unroll
        for (int w2 = 0; w2 < 8; w2++) v += sds[t][w2];
        sS[t] = v;
    }
    __syncthreads();

    if (t < 64) {
        float a = 0.f, b = 0.f;
        #pragma unroll
        for (int rl = 0; rl < RPB; rl++) {
            float p = sP[rl][t];
            b += p;
            a  = fmaf(p, sS[rl], a);
        }
        g_pA[t * NBLK + blockIdx.x] = a;     // transposed for coalesced K3 reads
        g_pB[t * NBLK + blockIdx.x] = b;
    }
    if (t == 0) {
        float v = 0.f;
        #pragma unroll
        for (int rl = 0; rl < RPB; rl++) v += sSel[rl];
        g_pSel[blockIdx.x] = v;
    }
}

// ---------------------------------------------------------------------------
// K3: reduce the 128 row-block partials -> col_ch = 1 - exp(L); per-block
// colch sums; warp-parallel reductions of pA/pB/sel; last block finalizes.
// Output layout (float32, concatenated tuple):
//   P[131072] | tot[8] | max_nnz[8] | num_col[8] | num_row[8] |
//   nnz_ch_ba[64] | col_density[8] | num_row_sel[1]
// ---------------------------------------------------------------------------
__global__ __launch_bounds__(256) void k3_reduce_final(float* __restrict__ out)
{
    const int t    = threadIdx.x;
    const int lane = t & 31;
    const int wid  = t >> 5;
    const int o    = blockIdx.x * 256 + t;   // (ch*1024 + c); block covers one ch

    // ---- sum 128 Lpart partials with 4-way MLP ----
    float s0 = 0.f, s1 = 0.f, s2 = 0.f, s3 = 0.f;
    #pragma unroll
    for (int k = 0; k < NBLK; k += 4) {
        s0 += g_Lpart[(k + 0) * (NCH * C_) + o];
        s1 += g_Lpart[(k + 1) * (NCH * C_) + o];
        s2 += g_Lpart[(k + 2) * (NCH * C_) + o];
        s3 += g_Lpart[(k + 3) * (NCH * C_) + o];
    }
    float colch = 1.0f - expf((s0 + s1) + (s2 + s3));

    // ---- block-sum of colch (all 256 lanes are the same channel) ----
    float v = colch;
    #pragma unroll
    for (int off = 16; off > 0; off >>= 1)
        v += __shfl_xor_sync(0xFFFFFFFFu, v, off);
    __shared__ float wsum[8];
    if (lane == 0) wsum[wid] = v;

    // ---- warp-parallel reductions of KF partials (coalesced, transposed) ----
    const int gw = blockIdx.x * 8 + wid;     // global warp id 0..255
    if (gw < 64) {
        float a = 0.f;
        #pragma unroll
        for (int k = 0; k < 4; k++) a += g_pA[gw * NBLK + lane + k * 32];
        #pragma unroll
        for (int off = 16; off > 0; off >>= 1)
            a += __shfl_xor_sync(0xFFFFFFFFu, a, off);
        if (lane == 0) g_nnz[gw] = a;
    } else if (gw < 128) {
        float a = 0.f;
        #pragma unroll
        for (int k = 0; k < 4; k++) a += g_pB[(gw - 64) * NBLK + lane + k * 32];
        #pragma unroll
        for (int off = 16; off > 0; off >>= 1)
            a += __shfl_xor_sync(0xFFFFFFFFu, a, off);
        if (lane == 0) g_psum[gw - 64] = a;
    } else if (gw == 128) {
        float a = 0.f;
        #pragma unroll
        for (int k = 0; k < 4; k++) a += g_pSel[lane + k * 32];
        #pragma unroll
        for (int off = 16; off > 0; off >>= 1)
            a += __shfl_xor_sync(0xFFFFFFFFu, a, off);
        if (lane == 0) g_selv = a;
    }

    __syncthreads();
    if (t == 0) {
        float bs = 0.f;
        #pragma unroll
        for (int w2 = 0; w2 < 8; w2++) bs += wsum[w2];
        g_ncolPart[blockIdx.x] = bs;
    }

    // ---- completion ticket: last block finalizes ----
    __shared__ int isLast;
    __threadfence();
    if (t == 0) {
        unsigned int old = atomicAdd(&g_count, 1u);
        isLast = (old == K3_BLOCKS - 1) ? 1 : 0;
        if (isLast) g_count = 0;             // reset for next graph replay
    }
    __syncthreads();
    if (!isLast) return;
    __threadfence();                          // acquire other blocks' writes

    if (t < 64) out[131104 + t] = g_nnz[t];   // nnz_ch_ba

    if (t < NCH) {
        float m = -1e30f, ns = 0.f, rs = 0.f;
        #pragma unroll
        for (int ba = 0; ba < 8; ba++) {
            float nv = g_nnz[t * 8 + ba];
            m  = fmaxf(m, nv);
            ns += nv;
            rs += g_psum[t * 8 + ba];
        }
        float ncl = g_ncolPart[t * 4] + g_ncolPart[t * 4 + 1]
                  + g_ncolPart[t * 4 + 2] + g_ncolPart[t * 4 + 3];
        out[131072 + t] = m + ncl + rs;       // tot_ch
        out[131080 + t] = m;                  // max_nnz_ch
        out[131088 + t] = ncl;                // num_col_ch
        out[131096 + t] = rs;                 // num_row_ch
        out[131168 + t] = ns / rs / ncl;      // col_density_ch
    }
    if (t == 0) out[131176] = g_selv;         // num_row_sel
}

// ---------------------------------------------------------------------------
extern "C" void kernel_launch(void* const* d_in, const int* in_sizes, int n_in,
                              void* d_out, int out_size)
{
    const float* W = (const float*)d_in[0];   // [2048, 64]
    const float* D = (const float*)d_in[1];   // [2048, 1024]
    const float* G = (const float*)d_in[2];   // [2048, 64]
    // d_in[3] = i, unused by the math
    float* out = (float*)d_out;

    kf_fused<<<NBLK, 256>>>(W, D, G, out);
    k3_reduce_final<<<K3_BLOCKS, 256>>>(out);
}

// round 4
// speedup vs baseline: 2.7034x; 1.3039x over previous
#include <cuda_runtime.h>
#include <math.h>

// Problem constants
#define R_    2048
#define C_    1024
#define NCH   8

#define RPB      16               // rows per fused block
#define NBLK     (R_ / RPB)       // 128  (also the # of Lpart partials)
#define NB3      128              // K3 grid

// Scratch (no allocations allowed -> device globals)
__device__ float g_Lpart[NBLK * NCH * C_];   // partial log-sums per row-block (4MB)
__device__ float g_pA[64 * NBLK];            // [col64][block128] sum_r P*s
__device__ float g_pB[64 * NBLK];            // [col64][block128] sum_r P
__device__ float g_pSel[NBLK];               // per-block partial row-sel count
__device__ float g_nnz[64];                  // reduced nnz_ch_ba
__device__ float g_psum[64];                 // reduced sum_r P per (ch,ba)
__device__ float g_ncolPart[NB3];            // per-K3-block colch sums
__device__ float g_selv;                     // reduced row-sel count
__device__ unsigned int g_count = 0;         // K3 completion ticket (self-resetting)

// ---------------------------------------------------------------------------
// KF (fused): each block owns 16 rows.
//  Stage A: 8 warps x 2 rows -> softmax over 64, write P, stage P/lq/sel in smem.
//  Stage B: stream the 16x1024 D tile ONCE; FMAs into 32 accumulators + per-row
//           sums kept in registers (no shfl inside the load loop).
//  Stage C: write Lpart + per-block pA/pB/sel partials.
// ---------------------------------------------------------------------------
__global__ __launch_bounds__(256) void kf_fused(const float* __restrict__ W,
                                                const float* __restrict__ D,
                                                const float* __restrict__ G,
                                                float* __restrict__ outP)
{
    __shared__ float sP[RPB][64];
    __shared__ float slq[RPB][NCH];
    __shared__ float sds[RPB][8];
    __shared__ float sSel[RPB];
    __shared__ float sS[RPB];

    const int t    = threadIdx.x;
    const int wid  = t >> 5;
    const int lane = t & 31;
    const int r0   = blockIdx.x * RPB;

    const float2* W2 = reinterpret_cast<const float2*>(W);
    const float2* G2 = reinterpret_cast<const float2*>(G);

    // ---- Stage A: softmax, 2 rows per warp ----
    #pragma unroll
    for (int rr = 0; rr < 2; rr++) {
        const int rl = wid * 2 + rr;
        const int r  = r0 + rl;

        float2 w  = W2[r * 32 + lane];
        float2 gv = G2[r * 32 + lane];
        float e0 = w.x + gv.x;
        float e1 = w.y + gv.y;

        float m = fmaxf(e0, e1);
        #pragma unroll
        for (int o = 16; o > 0; o >>= 1)
            m = fmaxf(m, __shfl_xor_sync(0xFFFFFFFFu, m, o));

        float x0 = expf(e0 - m);
        float x1 = expf(e1 - m);
        float s  = x0 + x1;
        #pragma unroll
        for (int o = 16; o > 0; o >>= 1)
            s += __shfl_xor_sync(0xFFFFFFFFu, s, o);

        const float inv = 1.0f / s;      // == max(P): exp(0)=1 at the argmax
        const float p0  = x0 * inv;
        const float p1  = x1 * inv;

        reinterpret_cast<float2*>(outP)[r * 32 + lane] = make_float2(p0, p1);
        sP[rl][2 * lane]     = p0;
        sP[rl][2 * lane + 1] = p1;

        float lq = log1pf(-p0) + log1pf(-p1);
        lq += __shfl_xor_sync(0xFFFFFFFFu, lq, 1);
        lq += __shfl_xor_sync(0xFFFFFFFFu, lq, 2);
        if ((lane & 3) == 0) slq[rl][lane >> 2] = lq;
        if (lane == 0) sSel[rl] = (inv > 0.99f) ? 1.0f : 0.0f;
    }
    __syncthreads();

    // ---- Stage B: single pass over the D tile (no shfl in the loop) ----
    float acc0[NCH], acc1[NCH], acc2[NCH], acc3[NCH];
    #pragma unroll
    for (int ch = 0; ch < NCH; ch++) { acc0[ch]=0.f; acc1[ch]=0.f; acc2[ch]=0.f; acc3[ch]=0.f; }
    float dsv[RPB];

    const float4* D4 = reinterpret_cast<const float4*>(D);
    #pragma unroll
    for (int rl = 0; rl < RPB; rl++) {
        float4 d = D4[(size_t)(r0 + rl) * 256 + t];
        dsv[rl] = (d.x + d.y) + (d.z + d.w);
        #pragma unroll
        for (int ch = 0; ch < NCH; ch++) {
            float l = slq[rl][ch];
            acc0[ch] = fmaf(d.x, l, acc0[ch]);
            acc1[ch] = fmaf(d.y, l, acc1[ch]);
            acc2[ch] = fmaf(d.z, l, acc2[ch]);
            acc3[ch] = fmaf(d.w, l, acc3[ch]);
        }
    }

    // per-row sums: warp-reduce the register array after the memory loop
    #pragma unroll
    for (int rl = 0; rl < RPB; rl++) {
        float v = dsv[rl];
        #pragma unroll
        for (int o = 16; o > 0; o >>= 1)
            v += __shfl_xor_sync(0xFFFFFFFFu, v, o);
        if (lane == 0) sds[rl][wid] = v;
    }

    // ---- Stage C: write partials ----
    const int c0 = t * 4;
    #pragma unroll
    for (int ch = 0; ch < NCH; ch++) {
        float4 v = make_float4(acc0[ch], acc1[ch], acc2[ch], acc3[ch]);
        *reinterpret_cast<float4*>(
            &g_Lpart[((size_t)blockIdx.x * NCH + ch) * C_ + c0]) = v;
    }
    __syncthreads();

    if (t < RPB) {
        float v = 0.f;
        #pragma unroll
        for (int w2 = 0; w2 < 8; w2++) v += sds[t][w2];
        sS[t] = v;
    }
    __syncthreads();

    if (t < 64) {
        float a = 0.f, b = 0.f;
        #pragma unroll
        for (int rl = 0; rl < RPB; rl++) {
            float p = sP[rl][t];
            b += p;
            a  = fmaf(p, sS[rl], a);
        }
        g_pA[t * NBLK + blockIdx.x] = a;     // row-major [64][128], coalesced in K3
        g_pB[t * NBLK + blockIdx.x] = b;
    }
    if (t == 0) {
        float v = 0.f;
        #pragma unroll
        for (int rl = 0; rl < RPB; rl++) v += sSel[rl];
        g_pSel[blockIdx.x] = v;
    }
}

// ---------------------------------------------------------------------------
// K3: grid 128. Block b owns 64 outputs o in [b*64, b*64+64) (one channel).
// 256 threads = 64 outputs x 4 k-groups; each thread sums 32 of the 128
// partials (coalesced). Idle warps 4/5/6 reduce pA/pB/sel. Last block
// finalizes all scalars.
// Output layout (float32, concatenated tuple):
//   P[131072] | tot[8] | max_nnz[8] | num_col[8] | num_row[8] |
//   nnz_ch_ba[64] | col_density[8] | num_row_sel[1]
// ---------------------------------------------------------------------------
__global__ __launch_bounds__(256) void k3_reduce_final(float* __restrict__ out)
{
    const int b    = blockIdx.x;
    const int t    = threadIdx.x;
    const int lane = t & 31;
    const int ol   = t & 63;          // output within block
    const int kg   = t >> 6;          // 0..3
    const int o    = b * 64 + ol;

    // ---- each thread sums 32 partials with 4 accumulators ----
    float s0 = 0.f, s1 = 0.f, s2 = 0.f, s3 = 0.f;
    const float* base = g_Lpart + (size_t)(kg * 32) * (NCH * C_) + o;
    #pragma unroll
    for (int j = 0; j < 32; j += 4) {
        s0 += base[(j + 0) * (NCH * C_)];
        s1 += base[(j + 1) * (NCH * C_)];
        s2 += base[(j + 2) * (NCH * C_)];
        s3 += base[(j + 3) * (NCH * C_)];
    }
    __shared__ float red[4][64];
    red[kg][ol] = (s0 + s1) + (s2 + s3);
    __syncthreads();

    // ---- warps 0-1: combine k-groups, colch = 1-exp, sum over the 64 outputs ----
    __shared__ float cs[2];
    if (t < 64) {
        float L = (red[0][t] + red[1][t]) + (red[2][t] + red[3][t]);
        float colch = 1.0f - expf(L);
        #pragma unroll
        for (int off = 16; off > 0; off >>= 1)
            colch += __shfl_xor_sync(0xFFFFFFFFu, colch, off);
        if (lane == 0) cs[t >> 5] = colch;
    }

    // ---- warps 4/5/6: reduce KF partials (blocks 0..64 only) ----
    const int wid = t >> 5;
    if (wid == 4 && b < 64) {                 // pA row b -> g_nnz[b]
        float a = g_pA[b * NBLK + lane]      + g_pA[b * NBLK + lane + 32]
                + g_pA[b * NBLK + lane + 64] + g_pA[b * NBLK + lane + 96];
        #pragma unroll
        for (int off = 16; off > 0; off >>= 1)
            a += __shfl_xor_sync(0xFFFFFFFFu, a, off);
        if (lane == 0) g_nnz[b] = a;
    } else if (wid == 5 && b < 64) {          // pB row b -> g_psum[b]
        float a = g_pB[b * NBLK + lane]      + g_pB[b * NBLK + lane + 32]
                + g_pB[b * NBLK + lane + 64] + g_pB[b * NBLK + lane + 96];
        #pragma unroll
        for (int off = 16; off > 0; off >>= 1)
            a += __shfl_xor_sync(0xFFFFFFFFu, a, off);
        if (lane == 0) g_psum[b] = a;
    } else if (wid == 6 && b == 64) {         // sel -> g_selv
        float a = g_pSel[lane]      + g_pSel[lane + 32]
                + g_pSel[lane + 64] + g_pSel[lane + 96];
        #pragma unroll
        for (int off = 16; off > 0; off >>= 1)
            a += __shfl_xor_sync(0xFFFFFFFFu, a, off);
        if (lane == 0) g_selv = a;
    }
    __syncthreads();

    if (t == 0) g_ncolPart[b] = cs[0] + cs[1];

    // ---- completion ticket: last block finalizes ----
    __shared__ int isLast;
    __threadfence();
    if (t == 0) {
        unsigned int old = atomicAdd(&g_count, 1u);
        isLast = (old == NB3 - 1) ? 1 : 0;
        if (isLast) g_count = 0;              // reset for next graph replay
    }
    __syncthreads();
    if (!isLast) return;
    __threadfence();                           // acquire other blocks' writes

    if (t < 64) out[131104 + t] = g_nnz[t];    // nnz_ch_ba

    if (t < NCH) {
        float m = -1e30f, ns = 0.f, rs = 0.f;
        #pragma unroll
        for (int ba = 0; ba < 8; ba++) {
            float nv = g_nnz[t * 8 + ba];
            m  = fmaxf(m, nv);
            ns += nv;
            rs += g_psum[t * 8 + ba];
        }
        float ncl = 0.f;
        #pragma unroll
        for (int k = 0; k < 16; k++) ncl += g_ncolPart[t * 16 + k];
        out[131072 + t] = m + ncl + rs;        // tot_ch
        out[131080 + t] = m;                   // max_nnz_ch
        out[131088 + t] = ncl;                 // num_col_ch
        out[131096 + t] = rs;                  // num_row_ch
        out[131168 + t] = ns / rs / ncl;       // col_density_ch
    }
    if (t == 0) out[131176] = g_selv;          // num_row_sel
}

// ---------------------------------------------------------------------------
extern "C" void kernel_launch(void* const* d_in, const int* in_sizes, int n_in,
                              void* d_out, int out_size)
{
    const float* W = (const float*)d_in[0];   // [2048, 64]
    const float* D = (const float*)d_in[1];   // [2048, 1024]
    const float* G = (const float*)d_in[2];   // [2048, 64]
    // d_in[3] = i, unused by the math
    float* out = (float*)d_out;

    kf_fused<<<NBLK, 256>>>(W, D, G, out);
    k3_reduce_final<<<NB3, 256>>>(out);
}